// round 5
// baseline (speedup 1.0000x reference)
#include <cuda_runtime.h>
#include <math.h>

#define BATCH 16
#define COUT 64
#define RANK 4
#define EPSBN 1e-5f

// layer geometry
#define H1IN 128
#define W1IN 256
#define HO1  130
#define WO1  258
#define HO2  132
#define WO2  260
#define POH  44
#define POW  86

// scratch (static device arrays — no allocations allowed)
__device__ float g_h1[(size_t)BATCH * COUT * HO1 * WO1];   // ~137 MB
__device__ float g_h2[(size_t)BATCH * COUT * HO2 * WO2];   // ~140 MB
__device__ float g_stats[4 * COUT];                        // sum1,sq1,sum2,sq2
__device__ float g_st[4 * COUT];                           // s1,t1,s2,t2

// ---- packed f32x2 helpers (sm_103a FFMA2 path; only reachable via PTX) ----
__device__ __forceinline__ unsigned long long pk2(float v) {
    unsigned long long d; unsigned u = __float_as_uint(v);
    asm("mov.b64 %0, {%1,%1};" : "=l"(d) : "r"(u));
    return d;
}
__device__ __forceinline__ unsigned long long fma2(unsigned long long a,
                                                   unsigned long long b,
                                                   unsigned long long c) {
    unsigned long long d;
    asm("fma.rn.f32x2 %0, %1, %2, %3;" : "=l"(d) : "l"(a), "l"(b), "l"(c));
    return d;
}
__device__ __forceinline__ unsigned long long mul2(unsigned long long a,
                                                   unsigned long long b) {
    unsigned long long d;
    asm("mul.rn.f32x2 %0, %1, %2;" : "=l"(d) : "l"(a), "l"(b));
    return d;
}
__device__ __forceinline__ unsigned long long add2(unsigned long long a,
                                                   unsigned long long b) {
    unsigned long long d;
    asm("add.rn.f32x2 %0, %1, %2;" : "=l"(d) : "l"(a), "l"(b));
    return d;
}
// split packed (w0,w1) into broadcast pairs (w0,w0) and (w1,w1)
__device__ __forceinline__ void dup2(unsigned long long v,
                                     unsigned long long& d0,
                                     unsigned long long& d1) {
    unsigned lo, hi;
    asm("mov.b64 {%0,%1}, %2;" : "=r"(lo), "=r"(hi) : "l"(v));
    asm("mov.b64 %0, {%1,%1};" : "=l"(d0) : "r"(lo));
    asm("mov.b64 %0, {%1,%1};" : "=l"(d1) : "r"(hi));
}
__device__ __forceinline__ float2 unpk(unsigned long long v) {
    unsigned lo, hi;
    asm("mov.b64 {%0,%1}, %2;" : "=r"(lo), "=r"(hi) : "l"(v));
    float2 f; f.x = __uint_as_float(lo); f.y = __uint_as_float(hi);
    return f;
}

__global__ void zero_stats_kernel() {
    int i = threadIdx.x;
    if (i < 4 * COUT) g_stats[i] = 0.f;
}

// Per-channel BN scale/shift from accumulated sums.
__global__ void finalize_stats_kernel(const float* __restrict__ sums,
                                      const float* __restrict__ gam,
                                      const float* __restrict__ bet,
                                      float* __restrict__ st, float N) {
    int c = threadIdx.x;
    if (c < COUT) {
        float mean = sums[c] / N;
        float var  = sums[COUT + c] / N - mean * mean;
        float s    = gam[c] * rsqrtf(var + EPSBN);
        st[c]         = s;
        st[COUT + c]  = bet[c] - mean * s;
    }
}

// LRLC conv with cw-folded weights, f32x2 packed math over batch pairs.
// One CTA: one output row h, 32 output cols, 32 out channels (half, by blockIdx.z),
// all 16 batch. Two CTAs per (h, tile) -> 2 CTAs/SM with independent barriers
// for latency overlap (RF: 2 * 256 * 128 regs = full).
// Thread (tx, og): pixel (h, w0+tx), channels oofs+og*4.., all 16 batch
//   -> 32 packed accumulators (64 fp32).
// wsm layout: [kl(72)][r(4)][o(32)]
template<int CIN, int HIN, int WIN, int HO, int WO, bool FUSED>
__global__ __launch_bounds__(256, 2)
void lrlc_conv_kernel(const float* __restrict__ xin,
                      const float* __restrict__ wgt,   // [r][o][ci][3][3]
                      const float* __restrict__ bias,
                      const float* __restrict__ ah,    // [r][HO]
                      const float* __restrict__ aw,    // [r][WO]
                      const float* __restrict__ st,    // s[64],t[64] (FUSED only)
                      float* __restrict__ yout,        // [b][o][HO][WO]
                      float* __restrict__ stats)       // sum[64], sumsq[64]
{
    extern __shared__ float sm[];
    float* wsm = sm;                    // [72][4][32] = 9216 floats
    float* xsm = sm + 72 * 128;         // [8 cl][3 kh][4 bg][34 col][4 b4] = 13056 floats

    const int tx   = threadIdx.x;       // 0..31  (w lane)
    const int og   = threadIdx.y;       // 0..7   (channel group within half)
    const int tid  = og * 32 + tx;
    const int lane = tx;
    const int wid  = og;

    const int h    = blockIdx.y;
    const int w0   = blockIdx.x * 32;
    const int oofs = blockIdx.z * 32;   // which o-half this CTA owns
    const int wq = w0 + tx;
    const bool wvalid = (wq < WO);
    const int wc = wvalid ? wq : (WO - 1);

    // combining weights (softmax over rank), packed for f32x2 fold
    float lg[RANK];
#pragma unroll
    for (int r = 0; r < RANK; ++r)
        lg[r] = ah[r * HO + h] + aw[r * WO + wc];
    float mx = fmaxf(fmaxf(lg[0], lg[1]), fmaxf(lg[2], lg[3]));
    float cw[RANK];
    float esum = 0.f;
#pragma unroll
    for (int r = 0; r < RANK; ++r) { cw[r] = expf(lg[r] - mx); esum += cw[r]; }
    float einv = 1.f / esum;
    unsigned long long cwp[RANK];
#pragma unroll
    for (int r = 0; r < RANK; ++r) cwp[r] = pk2(cw[r] * einv);

    unsigned long long acc[32];         // [j(4)][bg(4)][half(2)] packed fp32 pairs
#pragma unroll
    for (int i = 0; i < 32; ++i) acc[i] = 0ull;

    const int obl = og * 4;             // local o base (0..28)

    for (int cc = 0; cc < CIN / 8; ++cc) {
        __syncthreads();

        // ---- stage weights: wsm[kl*128 + r*32 + ol]  (72*32 = 2304 = 9*256)
#pragma unroll
        for (int mIt = 0; mIt < 9; ++mIt) {
            int p  = tid + mIt * 256;
            int ol = p & 31;
            int kl = p >> 5;
            int o  = oofs + ol;
#pragma unroll
            for (int r = 0; r < RANK; ++r)
                wsm[kl * 128 + r * 32 + ol] =
                    wgt[(r * COUT + o) * (CIN * 9) + cc * 72 + kl];
        }

        // ---- stage x: xsm[(((cl*3+kh)*4+bg)*34+col)*4 + b4]
        for (int s = wid; s < 384; s += 8) {
            int b   = s & 15;
            int rc  = s >> 4;          // 0..23
            int cl  = rc / 3;
            int kh  = rc - cl * 3;
            int row = h - 2 + kh;
            int cin = cc * 8 + cl;
            const float* src = xin + ((size_t)(b * CIN + cin) * HIN + row) * WIN;
            float sc = 0.f, tc = 0.f;
            if (FUSED) { sc = st[cin]; tc = st[COUT + cin]; }
            int base = (((cl * 3 + kh) * 4 + (b >> 2)) * 34) * 4 + (b & 3);
            bool rowok = (row >= 0) && (row < HIN);

            {
                int col = w0 - 2 + lane;
                bool ok = rowok && (col >= 0) && (col < WIN);
                float v = ok ? src[col] : 0.f;
                if (FUSED) v = ok ? fmaxf(v * sc + tc, 0.f) : 0.f;
                xsm[base + lane * 4] = v;
            }
            if (lane < 2) {
                int col_l2 = lane + 32;
                int col = w0 - 2 + col_l2;
                bool ok = rowok && (col >= 0) && (col < WIN);
                float v = ok ? src[col] : 0.f;
                if (FUSED) v = ok ? fmaxf(v * sc + tc, 0.f) : 0.f;
                xsm[base + col_l2 * 4] = v;
            }
        }

        __syncthreads();

        // ---- main compute (packed f32x2)
#pragma unroll 1
        for (int cl = 0; cl < 8; ++cl) {
#pragma unroll
            for (int kh = 0; kh < 3; ++kh) {
                const float* xrow = &xsm[(((cl * 3 + kh) * 4) * 34) * 4];
#pragma unroll
                for (int kw = 0; kw < 3; ++kw) {
                    int kl = cl * 9 + kh * 3 + kw;
                    const int kb = kl * 128 + obl;
                    // fold (tree): weff = (cw0 w0 + cw1 w1) + (cw2 w2 + cw3 w3)
                    ulonglong2 wr0 = *(const ulonglong2*)&wsm[kb];
                    ulonglong2 wr1 = *(const ulonglong2*)&wsm[kb + 32];
                    ulonglong2 wr2 = *(const ulonglong2*)&wsm[kb + 64];
                    ulonglong2 wr3 = *(const ulonglong2*)&wsm[kb + 96];
                    unsigned long long tA0 = mul2(cwp[0], wr0.x);
                    unsigned long long tB0 = mul2(cwp[0], wr0.y);
                    unsigned long long tA1 = mul2(cwp[2], wr2.x);
                    unsigned long long tB1 = mul2(cwp[2], wr2.y);
                    tA0 = fma2(cwp[1], wr1.x, tA0);
                    tB0 = fma2(cwp[1], wr1.y, tB0);
                    tA1 = fma2(cwp[3], wr3.x, tA1);
                    tB1 = fma2(cwp[3], wr3.y, tB1);
                    unsigned long long wA = add2(tA0, tA1);
                    unsigned long long wB = add2(tB0, tB1);
                    unsigned long long d0, d1, d2, d3;
                    dup2(wA, d0, d1);
                    dup2(wB, d2, d3);
#pragma unroll
                    for (int bg = 0; bg < 4; ++bg) {
                        ulonglong2 xv = *(const ulonglong2*)&xrow[(bg * 34 + tx + kw) * 4];
                        acc[0 * 8 + bg * 2 + 0] = fma2(d0, xv.x, acc[0 * 8 + bg * 2 + 0]);
                        acc[0 * 8 + bg * 2 + 1] = fma2(d0, xv.y, acc[0 * 8 + bg * 2 + 1]);
                        acc[1 * 8 + bg * 2 + 0] = fma2(d1, xv.x, acc[1 * 8 + bg * 2 + 0]);
                        acc[1 * 8 + bg * 2 + 1] = fma2(d1, xv.y, acc[1 * 8 + bg * 2 + 1]);
                        acc[2 * 8 + bg * 2 + 0] = fma2(d2, xv.x, acc[2 * 8 + bg * 2 + 0]);
                        acc[2 * 8 + bg * 2 + 1] = fma2(d2, xv.y, acc[2 * 8 + bg * 2 + 1]);
                        acc[3 * 8 + bg * 2 + 0] = fma2(d3, xv.x, acc[3 * 8 + bg * 2 + 0]);
                        acc[3 * 8 + bg * 2 + 1] = fma2(d3, xv.y, acc[3 * 8 + bg * 2 + 1]);
                    }
                }
            }
        }
    }

    // ---- epilogue: bias, store, BN-stat accumulation
#pragma unroll
    for (int j = 0; j < 4; ++j) {
        int o = oofs + obl + j;
        float bia = bias[o];
        float s0 = 0.f, s1 = 0.f;
#pragma unroll
        for (int bg = 0; bg < 4; ++bg) {
#pragma unroll
            for (int hf = 0; hf < 2; ++hf) {
                float2 vv = unpk(acc[j * 8 + bg * 2 + hf]);
                int b = bg * 4 + hf * 2;
                float v0 = vv.x + bia;
                float v1 = vv.y + bia;
                if (wvalid) {
                    yout[((size_t)((b + 0) * COUT + o) * HO + h) * WO + wq] = v0;
                    yout[((size_t)((b + 1) * COUT + o) * HO + h) * WO + wq] = v1;
                }
                float m0 = wvalid ? v0 : 0.f;
                float m1 = wvalid ? v1 : 0.f;
                s0 += m0 + m1;
                s1 += m0 * m0 + m1 * m1;
            }
        }
#pragma unroll
        for (int off = 16; off > 0; off >>= 1) {
            s0 += __shfl_xor_sync(0xffffffffu, s0, off);
            s1 += __shfl_xor_sync(0xffffffffu, s1, off);
        }
        if (lane == 0) {
            atomicAdd(&stats[o], s0);
            atomicAdd(&stats[COUT + o], s1);
        }
    }
}

// BN + ReLU + 3x3/3 maxpool (all candidates >= 0 after relu, so init 0 is exact)
__global__ void bn_relu_pool_kernel(const float* __restrict__ h2,
                                    const float* __restrict__ st,
                                    float* __restrict__ out) {
    int idx = blockIdx.x * blockDim.x + threadIdx.x;
    const int total = BATCH * COUT * POH * POW;
    if (idx >= total) return;
    int ow = idx % POW;
    int t  = idx / POW;
    int oh = t % POH;  t /= POH;
    int c  = t % COUT;
    int b  = t / COUT;
    float s  = st[c];
    float tt = st[COUT + c];
    const float* p = h2 + ((size_t)(b * COUT + c) * HO2 + oh * 3) * WO2 + ow * 3;
    float v = 0.f;
#pragma unroll
    for (int kh = 0; kh < 3; ++kh)
#pragma unroll
        for (int kw = 0; kw < 3; ++kw) {
            float u = fmaxf(p[kh * WO2 + kw] * s + tt, 0.f);
            v = fmaxf(v, u);
        }
    out[idx] = v;
}

extern "C" void kernel_launch(void* const* d_in, const int* in_sizes, int n_in,
                              void* d_out, int out_size) {
    const float* x   = (const float*)d_in[0];
    const float* w1  = (const float*)d_in[1];
    const float* b1  = (const float*)d_in[2];
    const float* a1h = (const float*)d_in[3];
    const float* a1w = (const float*)d_in[4];
    const float* g1  = (const float*)d_in[5];
    const float* be1 = (const float*)d_in[6];
    const float* w2  = (const float*)d_in[7];
    const float* b2  = (const float*)d_in[8];
    const float* a2h = (const float*)d_in[9];
    const float* a2w = (const float*)d_in[10];
    const float* g2  = (const float*)d_in[11];
    const float* be2 = (const float*)d_in[12];

    float *h1, *h2, *stats, *st;
    cudaGetSymbolAddress((void**)&h1, g_h1);
    cudaGetSymbolAddress((void**)&h2, g_h2);
    cudaGetSymbolAddress((void**)&stats, g_stats);
    cudaGetSymbolAddress((void**)&st, g_st);

    const size_t smem = (size_t)(72 * 128 + 8 * 3 * 4 * 34 * 4) * sizeof(float); // 89,088 B
    cudaFuncSetAttribute(lrlc_conv_kernel<32, 128, 256, 130, 258, false>,
                         cudaFuncAttributeMaxDynamicSharedMemorySize, (int)smem);
    cudaFuncSetAttribute(lrlc_conv_kernel<64, 130, 258, 132, 260, true>,
                         cudaFuncAttributeMaxDynamicSharedMemorySize, (int)smem);

    zero_stats_kernel<<<1, 256>>>();

    dim3 blk(32, 8);
    // layer 1: 258 cols -> 9 tiles of 32; z = o-half
    lrlc_conv_kernel<32, 128, 256, 130, 258, false>
        <<<dim3(9, 130, 2), blk, smem>>>(x, w1, b1, a1h, a1w, nullptr, h1, stats);
    finalize_stats_kernel<<<1, 64>>>(stats, g1, be1, st, (float)(BATCH * 130 * 258));

    // layer 2: 260 cols -> 9 tiles (input BN+ReLU fused during staging)
    lrlc_conv_kernel<64, 130, 258, 132, 260, true>
        <<<dim3(9, 132, 2), blk, smem>>>(h1, w2, b2, a2h, a2w, st, h2, stats + 128);
    finalize_stats_kernel<<<1, 64>>>(stats + 128, g2, be2, st + 128, (float)(BATCH * 132 * 260));

    const int total = BATCH * COUT * POH * POW;
    bn_relu_pool_kernel<<<(total + 255) / 256, 256>>>(h2, st + 128, (float*)d_out);
}

// round 7
// speedup vs baseline: 1.6475x; 1.6475x over previous
#include <cuda_runtime.h>
#include <cuda_fp16.h>
#include <math.h>
#include <stdint.h>

#define EPSBN 1e-5f

// layer geometry
#define HO1 130
#define WO1 258
#define HO2 132
#define WO2 260
#define TOT1 (16 * HO1 * WO1)
#define TOT2 (16 * HO2 * WO2)

// fp16 NHWC halo buffers (64 ch, 2-px halo each side)
__device__ __half g_xb1[(size_t)16 * 132 * 260 * 64];
__device__ __half g_xb2[(size_t)16 * 134 * 262 * 64];
__device__ __half g_y2 [(size_t)16 * 136 * 264 * 64];
// packed A blocks: [mh(2)][tap(9)][hl(2)][m(128)][72 ci-padded] fp16
__device__ __half g_apk1[2 * 9 * 2 * 128 * 72];
__device__ __half g_apk2[2 * 9 * 2 * 128 * 72];
__device__ float  g_stats[4 * 64];
__device__ float  g_st[4 * 64];

// ---- helpers ----
__device__ __forceinline__ uint32_t smem_u32(const void* p) {
    uint32_t a;
    asm("{ .reg .u64 t; cvta.to.shared.u64 t, %1; cvt.u32.u64 %0, t; }" : "=r"(a) : "l"(p));
    return a;
}
#define LDSM4(r, addr) \
    asm volatile("ldmatrix.sync.aligned.m8n8.x4.shared.b16 {%0,%1,%2,%3}, [%4];" \
        : "=r"((r)[0]), "=r"((r)[1]), "=r"((r)[2]), "=r"((r)[3]) : "r"(addr))

__device__ __forceinline__ void hmma(float* c, const uint32_t* a, const uint32_t* b) {
    asm volatile(
        "mma.sync.aligned.m16n8k16.row.col.f32.f16.f16.f32 "
        "{%0,%1,%2,%3}, {%4,%5,%6,%7}, {%8,%9}, {%0,%1,%2,%3};"
        : "+f"(c[0]), "+f"(c[1]), "+f"(c[2]), "+f"(c[3])
        : "r"(a[0]), "r"(a[1]), "r"(a[2]), "r"(a[3]), "r"(b[0]), "r"(b[1]));
}

// SMEM byte offsets
#define SM_BSM  0                      // 3*130 rows * 144B = 56160
#define SM_ASM  56160                  // 2*128 rows * 144B = 36864
#define SM_CWS  93024                  // 4*128 f = 2048
#define SM_BIA  95072                  // 32 f = 128
#define SM_YSM  95232                  // 128*32 half = 8192
#define SM_PP   103424                 // 8*32 float2 = 2048
#define SMEMSZ  105472

// ---- aux kernels ----
__global__ void k_zero(uint4* p, size_t n) {
    size_t i = (size_t)blockIdx.x * blockDim.x + threadIdx.x;
    size_t st = (size_t)gridDim.x * blockDim.x;
    uint4 z = make_uint4(0, 0, 0, 0);
    for (; i < n; i += st) p[i] = z;
}
__global__ void k_zero_stats() {
    if (threadIdx.x < 4 * 64) g_stats[threadIdx.x] = 0.f;
}
__global__ void k_finalize(const float* __restrict__ sums, const float* __restrict__ gam,
                           const float* __restrict__ bet, float* __restrict__ st, float N) {
    int c = threadIdx.x;
    if (c < 64) {
        float mean = sums[c] / N;
        float var  = sums[64 + c] / N - mean * mean;
        float s    = gam[c] * rsqrtf(var + EPSBN);
        st[c]      = s;
        st[64 + c] = bet[c] - mean * s;
    }
}
// pack weights [r][64][CIN][3][3] fp32 -> [mh][tap][hl][m=o*4+r][72] fp16 (hi, lo)
__global__ void k_pack(const float* __restrict__ w, __half* __restrict__ apk, int CIN) {
    int idx = blockIdx.x * 256 + threadIdx.x;
    const int TOTP = 2 * 9 * 2 * 128 * 72;
    if (idx >= TOTP) return;
    int kq = idx % 72;
    int m  = (idx / 72) % 128;
    int hl = (idx / (72 * 128)) % 2;
    int kk = (idx / (72 * 128 * 2)) % 9;
    int mh = idx / (72 * 128 * 2 * 9);
    int r = m & 3, o = mh * 32 + (m >> 2);
    int kh = kk / 3, kw = kk - kh * 3;
    float v = 0.f;
    if (kq < CIN) v = w[(((r * 64 + o) * CIN + kq) * 3 + kh) * 3 + kw];
    __half hi = __float2half(v);
    apk[idx] = (hl == 0) ? hi : __float2half(v - __half2float(hi));
}
// x NCHW fp32 -> xb1 NHWC fp16 halo (channels 32..63 stay zero)
__global__ __launch_bounds__(256) void k_tin(const float4* __restrict__ x4,
                                             __half* __restrict__ xb) {
    __shared__ __half ts[32][264];
    int tid = threadIdx.x;
    int b = blockIdx.x >> 7;
    int h = blockIdx.x & 127;
#pragma unroll
    for (int it = 0; it < 8; ++it) {
        int idx = tid + it * 256;
        int c = idx >> 6, w4 = idx & 63;
        float4 v = x4[((size_t)(b * 32 + c) * 128 + h) * 64 + w4];
        ts[c][w4 * 4 + 0] = __float2half(v.x);
        ts[c][w4 * 4 + 1] = __float2half(v.y);
        ts[c][w4 * 4 + 2] = __float2half(v.z);
        ts[c][w4 * 4 + 3] = __float2half(v.w);
    }
    __syncthreads();
    int w = tid;
    __half tmp[32];
#pragma unroll
    for (int c = 0; c < 32; ++c) tmp[c] = ts[c][w];
    uint4* dst = (uint4*)(xb + ((size_t)(b * 132 + h + 2) * 260 + (w + 2)) * 64);
#pragma unroll
    for (int q = 0; q < 4; ++q) dst[q] = ((uint4*)tmp)[q];
}
// BN1 + ReLU in place on xb2 interior
__global__ void k_bnrelu(__half* __restrict__ xb, const float* __restrict__ st) {
    int idx = blockIdx.x * blockDim.x + threadIdx.x;
    const int n = 16 * 130 * 258 * 8;
    if (idx >= n) return;
    int c8 = idx & 7;
    int rem = idx >> 3;
    int w = rem % 258; rem /= 258;
    int h = rem % 130;
    int b = rem / 130;
    __half* p = xb + ((size_t)(b * 134 + h + 2) * 262 + (w + 2)) * 64 + c8 * 8;
    uint4 v = *(uint4*)p;
    __half* hv = (__half*)&v;
#pragma unroll
    for (int j = 0; j < 8; ++j) {
        int c = c8 * 8 + j;
        float f = __half2float(hv[j]) * st[c] + st[64 + c];
        hv[j] = __float2half(fmaxf(f, 0.f));
    }
    *(uint4*)p = v;
}
// BN2 + ReLU + 3x3/3 maxpool -> NCHW fp32 out
__global__ void k_pool(const __half* __restrict__ y2, const float* __restrict__ st,
                       float* __restrict__ out) {
    int idx = blockIdx.x * blockDim.x + threadIdx.x;
    const int n = 16 * 44 * 86 * 8;
    if (idx >= n) return;
    int c8 = idx & 7;
    int rem = idx >> 3;
    int ow = rem % 86; rem /= 86;
    int oh = rem % 44;
    int b = rem / 44;
    float acc[8];
#pragma unroll
    for (int j = 0; j < 8; ++j) acc[j] = 0.f;
#pragma unroll
    for (int kh = 0; kh < 3; ++kh)
#pragma unroll
        for (int kw = 0; kw < 3; ++kw) {
            const __half* p = y2 + ((size_t)(b * 136 + oh * 3 + kh + 2) * 264
                                    + (ow * 3 + kw + 2)) * 64 + c8 * 8;
            uint4 v = *(const uint4*)p;
            const __half* hv = (const __half*)&v;
#pragma unroll
            for (int j = 0; j < 8; ++j) {
                int c = c8 * 8 + j;
                float f = __half2float(hv[j]) * st[c] + st[64 + c];
                acc[j] = fmaxf(acc[j], fmaxf(f, 0.f));
            }
        }
#pragma unroll
    for (int j = 0; j < 8; ++j) {
        int c = c8 * 8 + j;
        out[((size_t)(b * 64 + c) * 44 + oh) * 86 + ow] = acc[j];
    }
}

// ---- main conv: warp-MMA implicit GEMM (fp16 HMMA, fp32 acc, w hi+lo) ----
// CTA: one output row h, 128 px (wtile), M=128 (=32 o x 4 r, mh half), all taps.
// 8 warps: warp tile m32 x n64.
template<int KCI>
__global__ __launch_bounds__(256, 2)
void k_conv(const __half* __restrict__ xb, const __half* __restrict__ apk,
            const float* __restrict__ bias, const float* __restrict__ ah,
            const float* __restrict__ aw, __half* __restrict__ yb,
            float* __restrict__ stats,
            int HO, int WO, int HpIn, int WpIn, int HpOut, int WpOut)
{
    constexpr int KSTEPS = KCI / 16;
    constexpr int NU4 = KCI / 8;
    extern __shared__ char smraw[];
    char* bsm = smraw + SM_BSM;
    float* cws = (float*)(smraw + SM_CWS);
    float* bias_s = (float*)(smraw + SM_BIA);
    __half* ysm = (__half*)(smraw + SM_YSM);
    float2* pp = (float2*)(smraw + SM_PP);
    const uint32_t SB = smem_u32(smraw);

    const int tid = threadIdx.x;
    const int lane = tid & 31;
    const int wid = tid >> 5;
    const int h  = blockIdx.y;
    const int w0 = blockIdx.x * 128;
    const int b  = blockIdx.z >> 1;
    const int mh = blockIdx.z & 1;
    const int npx = min(128, WO - w0);

    // stage B: 3 input-row strips x 130 px x KCI ci (144B pitch)
    for (int i = tid; i < 3 * 130 * NU4; i += 256) {
        int q = i % NU4;
        int p = i / NU4;
        int strip = p / 130, c = p - strip * 130;
        int col = min(w0 + c, WpIn - 1);
        const uint4* src = (const uint4*)(xb +
            ((size_t)(b * HpIn + h + strip) * WpIn + col) * 64) + q;
        *(uint4*)(bsm + p * 144 + q * 16) = *src;
    }
    // combining weights (softmax over rank) per pixel
    if (tid < 128) {
        int w = min(w0 + tid, WO - 1);
        float lg[4], mx = -1e30f;
#pragma unroll
        for (int r = 0; r < 4; ++r) { lg[r] = ah[r * HO + h] + aw[r * WO + w]; mx = fmaxf(mx, lg[r]); }
        float es = 0.f;
#pragma unroll
        for (int r = 0; r < 4; ++r) { lg[r] = expf(lg[r] - mx); es += lg[r]; }
        float inv = 1.f / es;
#pragma unroll
        for (int r = 0; r < 4; ++r) cws[r * 128 + tid] = lg[r] * inv;
    }
    if (tid < 32) bias_s[tid] = bias[mh * 32 + tid];

    float acc[2][8][4];
#pragma unroll
    for (int mi = 0; mi < 2; ++mi)
#pragma unroll
        for (int ni = 0; ni < 8; ++ni)
#pragma unroll
            for (int c = 0; c < 4; ++c) acc[mi][ni][c] = 0.f;

    const int moff = (wid >> 1) * 32;
    const int noff = (wid & 1) * 64;
    const int arow = lane & 15;
    const int acol16 = (lane >> 4) * 16;
    const int brow = (lane & 7) + ((lane >> 4) << 3);
    const int bcol16 = ((lane >> 3) & 1) * 16;
    const uint32_t a_base = SB + SM_ASM + (moff + arow) * 144 + acol16;

#pragma unroll 1
    for (int kk = 0; kk < 9; ++kk) {
        // stage A (hi+lo blocks, 36864B = 2304 uint4)
        {
            const uint4* srcA = (const uint4*)(apk + (size_t)((mh * 9 + kk) * 2) * 128 * 72);
            uint4* dstA = (uint4*)(smraw + SM_ASM);
#pragma unroll
            for (int i = 0; i < 9; ++i) dstA[tid + i * 256] = srcA[tid + i * 256];
        }
        __syncthreads();
        const int kh = kk / 3, kw = kk - kh * 3;
        const uint32_t b_base = SB + (kh * 130 + noff + brow + kw) * 144 + bcol16;
#pragma unroll
        for (int s = 0; s < KSTEPS; ++s) {
            uint32_t bf[4][4];
#pragma unroll
            for (int n2 = 0; n2 < 4; ++n2)
                LDSM4(bf[n2], b_base + n2 * (16 * 144) + s * 32);
            uint32_t ahh[2][4], alo[2][4];
#pragma unroll
            for (int mi = 0; mi < 2; ++mi) {
                LDSM4(ahh[mi], a_base + mi * (16 * 144) + s * 32);
                LDSM4(alo[mi], a_base + 128 * 144 + mi * (16 * 144) + s * 32);
            }
#pragma unroll
            for (int mi = 0; mi < 2; ++mi)
#pragma unroll
                for (int ni = 0; ni < 8; ++ni) {
                    const uint32_t* bp = &bf[ni >> 1][(ni & 1) * 2];
                    hmma(acc[mi][ni], ahh[mi], bp);
                    hmma(acc[mi][ni], alo[mi], bp);
                }
        }
        __syncthreads();
    }

    // ---- epilogue: rank combine (shfl over r), bias, fp16 to ysm ----
    const int r4 = (lane >> 2) & 3;
    const bool lead = (r4 == 0);
#pragma unroll
    for (int mi = 0; mi < 2; ++mi)
#pragma unroll
        for (int ni = 0; ni < 8; ++ni) {
            int px0 = noff + 8 * ni + 2 * (lane & 3);
            float v0 = acc[mi][ni][0] * cws[r4 * 128 + px0];
            float v1 = acc[mi][ni][1] * cws[r4 * 128 + px0 + 1];
            float v2 = acc[mi][ni][2] * cws[r4 * 128 + px0];
            float v3 = acc[mi][ni][3] * cws[r4 * 128 + px0 + 1];
            v0 += __shfl_xor_sync(~0u, v0, 4); v0 += __shfl_xor_sync(~0u, v0, 8);
            v1 += __shfl_xor_sync(~0u, v1, 4); v1 += __shfl_xor_sync(~0u, v1, 8);
            v2 += __shfl_xor_sync(~0u, v2, 4); v2 += __shfl_xor_sync(~0u, v2, 8);
            v3 += __shfl_xor_sync(~0u, v3, 4); v3 += __shfl_xor_sync(~0u, v3, 8);
            if (lead) {
                int o0 = (moff + 16 * mi + (lane >> 2)) >> 2;
                int o2 = o0 + 2;
                ysm[px0 * 32 + o0]       = __float2half(v0 + bias_s[o0]);
                ysm[(px0 + 1) * 32 + o0] = __float2half(v1 + bias_s[o0]);
                ysm[px0 * 32 + o2]       = __float2half(v2 + bias_s[o2]);
                ysm[(px0 + 1) * 32 + o2] = __float2half(v3 + bias_s[o2]);
            }
        }
    __syncthreads();

    // BN stats (valid px only)
    {
        int ol = tid & 31, pb = tid >> 5;
        float s0 = 0.f, s1 = 0.f;
#pragma unroll
        for (int jj = 0; jj < 16; ++jj) {
            int j = pb * 16 + jj;
            if (j < npx) {
                float v = __half2float(ysm[j * 32 + ol]);
                s0 += v; s1 += v * v;
            }
        }
        pp[pb * 32 + ol] = make_float2(s0, s1);
    }
    __syncthreads();
    if (tid < 32) {
        float a0 = 0.f, a1 = 0.f;
#pragma unroll
        for (int pb2 = 0; pb2 < 8; ++pb2) {
            float2 u = pp[pb2 * 32 + tid];
            a0 += u.x; a1 += u.y;
        }
        atomicAdd(&stats[mh * 32 + tid], a0);
        atomicAdd(&stats[64 + mh * 32 + tid], a1);
    }
    // store NHWC fp16 (this CTA's 32-ch half), halo offset +2
    for (int i = tid; i < npx * 4; i += 256) {
        int p = i >> 2, q = i & 3;
        *(uint4*)(yb + ((size_t)(b * HpOut + h + 2) * WpOut + (w0 + p + 2)) * 64
                  + mh * 32 + q * 8) = *(const uint4*)(ysm + p * 32 + q * 8);
    }
}

extern "C" void kernel_launch(void* const* d_in, const int* in_sizes, int n_in,
                              void* d_out, int out_size) {
    const float* x   = (const float*)d_in[0];
    const float* w1  = (const float*)d_in[1];
    const float* b1  = (const float*)d_in[2];
    const float* a1h = (const float*)d_in[3];
    const float* a1w = (const float*)d_in[4];
    const float* g1  = (const float*)d_in[5];
    const float* be1 = (const float*)d_in[6];
    const float* w2  = (const float*)d_in[7];
    const float* b2  = (const float*)d_in[8];
    const float* a2h = (const float*)d_in[9];
    const float* a2w = (const float*)d_in[10];
    const float* g2  = (const float*)d_in[11];
    const float* be2 = (const float*)d_in[12];

    __half *xb1, *xb2, *y2, *ap1, *ap2;
    float *stats, *st;
    cudaGetSymbolAddress((void**)&xb1, g_xb1);
    cudaGetSymbolAddress((void**)&xb2, g_xb2);
    cudaGetSymbolAddress((void**)&y2, g_y2);
    cudaGetSymbolAddress((void**)&ap1, g_apk1);
    cudaGetSymbolAddress((void**)&ap2, g_apk2);
    cudaGetSymbolAddress((void**)&stats, g_stats);
    cudaGetSymbolAddress((void**)&st, g_st);

    cudaFuncSetAttribute(k_conv<32>, cudaFuncAttributeMaxDynamicSharedMemorySize, SMEMSZ);
    cudaFuncSetAttribute(k_conv<64>, cudaFuncAttributeMaxDynamicSharedMemorySize, SMEMSZ);

    k_zero_stats<<<1, 256>>>();
    k_zero<<<4096, 256>>>((uint4*)xb1, (size_t)16 * 132 * 260 * 64 / 8);
    k_zero<<<4096, 256>>>((uint4*)xb2, (size_t)16 * 134 * 262 * 64 / 8);
    const int TOTP = 2 * 9 * 2 * 128 * 72;
    k_pack<<<(TOTP + 255) / 256, 256>>>(w1, ap1, 32);
    k_pack<<<(TOTP + 255) / 256, 256>>>(w2, ap2, 64);
    k_tin<<<16 * 128, 256>>>((const float4*)x, xb1);

    k_conv<32><<<dim3(3, HO1, 32), 256, SMEMSZ>>>(xb1, ap1, b1, a1h, a1w, xb2, stats,
                                                  HO1, WO1, 132, 260, 134, 262);
    k_finalize<<<1, 64>>>(stats, g1, be1, st, (float)TOT1);
    k_bnrelu<<<(16 * 130 * 258 * 8 + 255) / 256, 256>>>(xb2, st);

    k_conv<64><<<dim3(3, HO2, 32), 256, SMEMSZ>>>(xb2, ap2, b2, a2h, a2w, y2, stats + 128,
                                                  HO2, WO2, 134, 262, 136, 264);
    k_finalize<<<1, 64>>>(stats + 128, g2, be2, st + 128, (float)TOT2);

    k_pool<<<(16 * 44 * 86 * 8 + 255) / 256, 256>>>(y2, st + 128, (float*)d_out);
}

// round 8
// speedup vs baseline: 1.6740x; 1.0160x over previous
#include <cuda_runtime.h>
#include <cuda_fp16.h>
#include <math.h>
#include <stdint.h>

#define EPSBN 1e-5f

// layer geometry
#define HO1 130
#define WO1 258
#define HO2 132
#define WO2 260
#define TOT1 (16 * HO1 * WO1)
#define TOT2 (16 * HO2 * WO2)

// fp16 NHWC halo buffers (64 ch, 2-px halo each side)
__device__ __half g_xb1[(size_t)16 * 132 * 260 * 64];
__device__ __half g_xb2[(size_t)16 * 134 * 262 * 64];
__device__ __half g_y2 [(size_t)16 * 136 * 264 * 64];
// packed A blocks: [mh(2)][tap(9)][hl(2)][m(128)][KCI+8] fp16
__device__ __half g_apk1[2 * 9 * 2 * 128 * 40];
__device__ __half g_apk2[2 * 9 * 2 * 128 * 72];
__device__ float  g_stats[4 * 64];
__device__ float  g_st[4 * 64];

// ---- helpers ----
__device__ __forceinline__ uint32_t smem_u32(const void* p) {
    uint32_t a;
    asm("{ .reg .u64 t; cvta.to.shared.u64 t, %1; cvt.u32.u64 %0, t; }" : "=r"(a) : "l"(p));
    return a;
}
#define LDSM4(r, addr) \
    asm volatile("ldmatrix.sync.aligned.m8n8.x4.shared.b16 {%0,%1,%2,%3}, [%4];" \
        : "=r"((r)[0]), "=r"((r)[1]), "=r"((r)[2]), "=r"((r)[3]) : "r"(addr))

__device__ __forceinline__ void hmma(float* c, const uint32_t* a, const uint32_t* b) {
    asm volatile(
        "mma.sync.aligned.m16n8k16.row.col.f32.f16.f16.f32 "
        "{%0,%1,%2,%3}, {%4,%5,%6,%7}, {%8,%9}, {%0,%1,%2,%3};"
        : "+f"(c[0]), "+f"(c[1]), "+f"(c[2]), "+f"(c[3])
        : "r"(a[0]), "r"(a[1]), "r"(a[2]), "r"(a[3]), "r"(b[0]), "r"(b[1]));
}
__device__ __forceinline__ void cpa16(uint32_t d, const void* s) {
    asm volatile("cp.async.cg.shared.global [%0], [%1], 16;" :: "r"(d), "l"(s));
}
#define CP_COMMIT() asm volatile("cp.async.commit_group;" ::: "memory")
#define CP_WAIT1()  asm volatile("cp.async.wait_group 1;" ::: "memory")

// ---- aux kernels ----
__global__ void k_zero(uint4* p, size_t n) {
    size_t i = (size_t)blockIdx.x * blockDim.x + threadIdx.x;
    size_t st = (size_t)gridDim.x * blockDim.x;
    uint4 z = make_uint4(0, 0, 0, 0);
    for (; i < n; i += st) p[i] = z;
}
__global__ void k_zero_stats() {
    if (threadIdx.x < 4 * 64) g_stats[threadIdx.x] = 0.f;
}
__global__ void k_finalize(const float* __restrict__ sums, const float* __restrict__ gam,
                           const float* __restrict__ bet, float* __restrict__ st, float N) {
    int c = threadIdx.x;
    if (c < 64) {
        float mean = sums[c] / N;
        float var  = sums[64 + c] / N - mean * mean;
        float s    = gam[c] * rsqrtf(var + EPSBN);
        st[c]      = s;
        st[64 + c] = bet[c] - mean * s;
    }
}
// pack weights [r][64][CIN][3][3] fp32 -> [mh][tap][hl][m=o*4+r][CIN+8] fp16 (hi,lo)
__global__ void k_pack(const float* __restrict__ w, __half* __restrict__ apk,
                       int CIN, int PR) {
    int idx = blockIdx.x * 256 + threadIdx.x;
    const int TOTP = 2 * 9 * 2 * 128 * PR;
    if (idx >= TOTP) return;
    int kq = idx % PR;
    int m  = (idx / PR) % 128;
    int hl = (idx / (PR * 128)) % 2;
    int kk = (idx / (PR * 128 * 2)) % 9;
    int mh = idx / (PR * 128 * 2 * 9);
    int r = m & 3, o = mh * 32 + (m >> 2);
    int kh = kk / 3, kw = kk - kh * 3;
    float v = 0.f;
    if (kq < CIN) v = w[(((r * 64 + o) * CIN + kq) * 3 + kh) * 3 + kw];
    __half hi = __float2half(v);
    apk[idx] = (hl == 0) ? hi : __float2half(v - __half2float(hi));
}
// x NCHW fp32 -> xb1 NHWC fp16 halo (channels 32..63 stay zero)
__global__ __launch_bounds__(256) void k_tin(const float4* __restrict__ x4,
                                             __half* __restrict__ xb) {
    __shared__ __half ts[32][264];
    int tid = threadIdx.x;
    int b = blockIdx.x >> 7;
    int h = blockIdx.x & 127;
#pragma unroll
    for (int it = 0; it < 8; ++it) {
        int idx = tid + it * 256;
        int c = idx >> 6, w4 = idx & 63;
        float4 v = x4[((size_t)(b * 32 + c) * 128 + h) * 64 + w4];
        ts[c][w4 * 4 + 0] = __float2half(v.x);
        ts[c][w4 * 4 + 1] = __float2half(v.y);
        ts[c][w4 * 4 + 2] = __float2half(v.z);
        ts[c][w4 * 4 + 3] = __float2half(v.w);
    }
    __syncthreads();
    int w = tid;
    __half tmp[32];
#pragma unroll
    for (int c = 0; c < 32; ++c) tmp[c] = ts[c][w];
    uint4* dst = (uint4*)(xb + ((size_t)(b * 132 + h + 2) * 260 + (w + 2)) * 64);
#pragma unroll
    for (int q = 0; q < 4; ++q) dst[q] = ((uint4*)tmp)[q];
}
// BN2 + ReLU + 3x3/3 maxpool -> NCHW fp32 out
__global__ void k_pool(const __half* __restrict__ y2, const float* __restrict__ st,
                       float* __restrict__ out) {
    int idx = blockIdx.x * blockDim.x + threadIdx.x;
    const int n = 16 * 44 * 86 * 8;
    if (idx >= n) return;
    int c8 = idx & 7;
    int rem = idx >> 3;
    int ow = rem % 86; rem /= 86;
    int oh = rem % 44;
    int b = rem / 44;
    float acc[8];
#pragma unroll
    for (int j = 0; j < 8; ++j) acc[j] = 0.f;
#pragma unroll
    for (int kh = 0; kh < 3; ++kh)
#pragma unroll
        for (int kw = 0; kw < 3; ++kw) {
            const __half* p = y2 + ((size_t)(b * 136 + oh * 3 + kh + 2) * 264
                                    + (ow * 3 + kw + 2)) * 64 + c8 * 8;
            uint4 v = *(const uint4*)p;
            const __half* hv = (const __half*)&v;
#pragma unroll
            for (int j = 0; j < 8; ++j) {
                int c = c8 * 8 + j;
                float f = __half2float(hv[j]) * st[c] + st[64 + c];
                acc[j] = fmaxf(acc[j], fmaxf(f, 0.f));
            }
        }
#pragma unroll
    for (int j = 0; j < 8; ++j) {
        int c = c8 * 8 + j;
        out[((size_t)(b * 64 + c) * 44 + oh) * 86 + ow] = acc[j];
    }
}

// ---- main conv: warp-MMA implicit GEMM, 2 output rows/CTA, cp.async A pipeline ----
// CTA: rows (h0, h0+1), 128 px, M=128 (=32 o x 4 r, mh half). 8 warps m32 x n128.
// FUSED: apply BN(stl)+ReLU of previous layer while staging B (interior only).
template<int KCI, bool FUSED>
__global__ __launch_bounds__(256, 1)
void k_conv(const __half* __restrict__ xb, const __half* __restrict__ apk,
            const float* __restrict__ bias, const float* __restrict__ ah,
            const float* __restrict__ aw, const float* __restrict__ stl,
            __half* __restrict__ yb, float* __restrict__ stats,
            int HO, int WO, int HpIn, int WpIn, int HpOut, int WpOut)
{
    constexpr int PITCH  = 2 * KCI + 16;            // bytes per smem row
    constexpr int PRH    = KCI + 8;                 // halfs per packed-A row
    constexpr int ACH    = 2 * 128 * PITCH;         // per-tap A chunk (hi+lo)
    constexpr int KSTEPS = KCI / 16;
    constexpr int BU4    = KCI / 8;                 // uint4 per B px
    constexpr int SMB  = 0;
    constexpr int SMA  = 4 * 130 * PITCH;
    constexpr int SMCW = SMA + 2 * ACH;
    constexpr int SMBI = SMCW + 4096;
    constexpr int SMY  = SMBI + 128;
    constexpr int SMPP = SMY + 16384;

    extern __shared__ char smraw[];
    char* bsm = smraw + SMB;
    float* cws = (float*)(smraw + SMCW);            // [row2][r4][128]
    float* bias_s = (float*)(smraw + SMBI);
    __half* ysm = (__half*)(smraw + SMY);           // [256 px][32 ch]
    float2* pp = (float2*)(smraw + SMPP);
    const uint32_t SB = smem_u32(smraw);

    const int tid = threadIdx.x;
    const int lane = tid & 31;
    const int wid = tid >> 5;
    const int h0 = blockIdx.y * 2;
    const int w0 = blockIdx.x * 128;
    const int b  = blockIdx.z >> 1;
    const int mh = blockIdx.z & 1;
    const int npx = min(128, WO - w0);

    // prefetch A taps 0,1 (cp.async, double buffer)
    {
        constexpr int NU = ACH / 16;
#pragma unroll
        for (int t = 0; t < 2; ++t) {
            const char* src = (const char*)(apk + (size_t)((mh * 9 + t) * 2) * 128 * PRH);
            uint32_t dst = SB + SMA + t * ACH;
            for (int i = tid; i < NU; i += 256) cpa16(dst + i * 16, src + i * 16);
            CP_COMMIT();
        }
    }

    // stage B: 4 input-row strips x 130 px (BN+ReLU fused if FUSED, interior only)
    for (int i = tid; i < 4 * 130 * BU4; i += 256) {
        int q = i % BU4;
        int p = i / BU4;
        int strip = p / 130, c = p - strip * 130;
        int row = h0 + strip;
        int col = min(w0 + c, WpIn - 1);
        uint4 v = *((const uint4*)(xb + ((size_t)(b * HpIn + row) * WpIn + col) * 64) + q);
        if (FUSED) {
            if (row >= 2 && row < HpIn - 2 && col >= 2 && col < WpIn - 2) {
                __half* hv = (__half*)&v;
#pragma unroll
                for (int j = 0; j < 8; ++j) {
                    int ch = q * 8 + j;
                    float f = __half2float(hv[j]) * stl[ch] + stl[64 + ch];
                    hv[j] = __float2half(fmaxf(f, 0.f));
                }
            }
        }
        *(uint4*)(bsm + p * PITCH + q * 16) = v;
    }
    // combining weights (softmax over rank), 2 rows x 128 px
    {
        int rr = tid >> 7, c = tid & 127;
        int w = min(w0 + c, WO - 1);
        int hh = h0 + rr;
        float lg[4], mx = -1e30f;
#pragma unroll
        for (int r = 0; r < 4; ++r) { lg[r] = ah[r * HO + hh] + aw[r * WO + w]; mx = fmaxf(mx, lg[r]); }
        float es = 0.f;
#pragma unroll
        for (int r = 0; r < 4; ++r) { lg[r] = expf(lg[r] - mx); es += lg[r]; }
        float inv = 1.f / es;
#pragma unroll
        for (int r = 0; r < 4; ++r) cws[(rr * 4 + r) * 128 + c] = lg[r] * inv;
    }
    if (tid < 32) bias_s[tid] = bias[mh * 32 + tid];

    float acc[2][16][4];
#pragma unroll
    for (int mi = 0; mi < 2; ++mi)
#pragma unroll
        for (int ni = 0; ni < 16; ++ni)
#pragma unroll
            for (int c = 0; c < 4; ++c) acc[mi][ni][c] = 0.f;

    const int moff  = (wid >> 1) * 32;
    const int npair = wid & 1;                     // which output row this warp handles
    const int arow = lane & 15;
    const int acol16 = (lane >> 4) * 16;
    const int brow = (lane & 7) + ((lane >> 4) << 3);
    const int bcol16 = ((lane >> 3) & 1) * 16;
    const uint32_t a_base0 = SB + SMA + (moff + arow) * PITCH + acol16;

#pragma unroll 1
    for (int kk = 0; kk < 9; ++kk) {
        CP_WAIT1();
        __syncthreads();
        const int kh = kk / 3, kw = kk - (kk / 3) * 3;
        const uint32_t a_base = a_base0 + (kk & 1) * ACH;
        const uint32_t b_base = SB + ((kh + npair) * 130 + brow + kw) * PITCH + bcol16;
#pragma unroll
        for (int s = 0; s < KSTEPS; ++s) {
            uint32_t ahh[2][4], alo[2][4];
#pragma unroll
            for (int mi = 0; mi < 2; ++mi) {
                LDSM4(ahh[mi], a_base + mi * (16 * PITCH) + s * 32);
                LDSM4(alo[mi], a_base + 128 * PITCH + mi * (16 * PITCH) + s * 32);
            }
#pragma unroll
            for (int half = 0; half < 2; ++half) {
                uint32_t bf[4][4];
#pragma unroll
                for (int n2 = 0; n2 < 4; ++n2)
                    LDSM4(bf[n2], b_base + (half * 4 + n2) * (16 * PITCH) + s * 32);
#pragma unroll
                for (int mi = 0; mi < 2; ++mi)
#pragma unroll
                    for (int n8 = 0; n8 < 8; ++n8) {
                        const uint32_t* bp = &bf[n8 >> 1][(n8 & 1) * 2];
                        hmma(acc[mi][half * 8 + n8], ahh[mi], bp);
                        hmma(acc[mi][half * 8 + n8], alo[mi], bp);
                    }
            }
        }
        __syncthreads();
        if (kk + 2 < 9) {
            constexpr int NU = ACH / 16;
            const char* src = (const char*)(apk + (size_t)((mh * 9 + kk + 2) * 2) * 128 * PRH);
            uint32_t dst = SB + SMA + (kk & 1) * ACH;
            for (int i = tid; i < NU; i += 256) cpa16(dst + i * 16, src + i * 16);
            CP_COMMIT();
        }
    }

    // ---- epilogue: rank combine (shfl over r), bias, fp16 to ysm ----
    const int r4 = (lane >> 2) & 3;
    const bool lead = (r4 == 0);
    const float* cwr = &cws[npair * 4 * 128];
#pragma unroll
    for (int mi = 0; mi < 2; ++mi)
#pragma unroll
        for (int ni = 0; ni < 16; ++ni) {
            int px0 = 8 * ni + 2 * (lane & 3);
            float v0 = acc[mi][ni][0] * cwr[r4 * 128 + px0];
            float v1 = acc[mi][ni][1] * cwr[r4 * 128 + px0 + 1];
            float v2 = acc[mi][ni][2] * cwr[r4 * 128 + px0];
            float v3 = acc[mi][ni][3] * cwr[r4 * 128 + px0 + 1];
            v0 += __shfl_xor_sync(~0u, v0, 4); v0 += __shfl_xor_sync(~0u, v0, 8);
            v1 += __shfl_xor_sync(~0u, v1, 4); v1 += __shfl_xor_sync(~0u, v1, 8);
            v2 += __shfl_xor_sync(~0u, v2, 4); v2 += __shfl_xor_sync(~0u, v2, 8);
            v3 += __shfl_xor_sync(~0u, v3, 4); v3 += __shfl_xor_sync(~0u, v3, 8);
            if (lead) {
                int o0 = (moff + 16 * mi + (lane >> 2)) >> 2;
                int o2 = o0 + 2;
                __half* yr = ysm + (npair * 128 + px0) * 32;
                yr[o0]      = __float2half(v0 + bias_s[o0]);
                yr[32 + o0] = __float2half(v1 + bias_s[o0]);
                yr[o2]      = __float2half(v2 + bias_s[o2]);
                yr[32 + o2] = __float2half(v3 + bias_s[o2]);
            }
        }
    __syncthreads();

    // BN stats (valid px only; 256 px rows x 32 ch)
    {
        int ol = tid & 31, pb = tid >> 5;
        float s0 = 0.f, s1 = 0.f;
#pragma unroll
        for (int jj = 0; jj < 32; ++jj) {
            int j = pb * 32 + jj;
            if ((j & 127) < npx) {
                float v = __half2float(ysm[j * 32 + ol]);
                s0 += v; s1 += v * v;
            }
        }
        pp[pb * 32 + ol] = make_float2(s0, s1);
    }
    __syncthreads();
    if (tid < 32) {
        float a0 = 0.f, a1 = 0.f;
#pragma unroll
        for (int pb2 = 0; pb2 < 8; ++pb2) {
            float2 u = pp[pb2 * 32 + tid];
            a0 += u.x; a1 += u.y;
        }
        atomicAdd(&stats[mh * 32 + tid], a0);
        atomicAdd(&stats[64 + mh * 32 + tid], a1);
    }
    // store NHWC fp16 (this CTA's 32-ch half), both rows, halo offset +2
    for (int i = tid; i < npx * 8; i += 256) {
        int q = i & 3;
        int p = (i >> 2) % npx;
        int rr = i / (npx * 4);
        *(uint4*)(yb + ((size_t)(b * HpOut + h0 + rr + 2) * WpOut + (w0 + p + 2)) * 64
                  + mh * 32 + q * 8) = *(const uint4*)(ysm + (rr * 128 + p) * 32 + q * 8);
    }
}

extern "C" void kernel_launch(void* const* d_in, const int* in_sizes, int n_in,
                              void* d_out, int out_size) {
    const float* x   = (const float*)d_in[0];
    const float* w1  = (const float*)d_in[1];
    const float* b1  = (const float*)d_in[2];
    const float* a1h = (const float*)d_in[3];
    const float* a1w = (const float*)d_in[4];
    const float* g1  = (const float*)d_in[5];
    const float* be1 = (const float*)d_in[6];
    const float* w2  = (const float*)d_in[7];
    const float* b2  = (const float*)d_in[8];
    const float* a2h = (const float*)d_in[9];
    const float* a2w = (const float*)d_in[10];
    const float* g2  = (const float*)d_in[11];
    const float* be2 = (const float*)d_in[12];

    __half *xb1, *xb2, *y2, *ap1, *ap2;
    float *stats, *st;
    cudaGetSymbolAddress((void**)&xb1, g_xb1);
    cudaGetSymbolAddress((void**)&xb2, g_xb2);
    cudaGetSymbolAddress((void**)&y2, g_y2);
    cudaGetSymbolAddress((void**)&ap1, g_apk1);
    cudaGetSymbolAddress((void**)&ap2, g_apk2);
    cudaGetSymbolAddress((void**)&stats, g_stats);
    cudaGetSymbolAddress((void**)&st, g_st);

    const int SM1 = 4 * 130 * 80 + 2 * (2 * 128 * 80) + 4096 + 128 + 16384 + 2048;
    const int SM2 = 4 * 130 * 144 + 2 * (2 * 128 * 144) + 4096 + 128 + 16384 + 2048;
    cudaFuncSetAttribute(k_conv<32, false>, cudaFuncAttributeMaxDynamicSharedMemorySize, SM1);
    cudaFuncSetAttribute(k_conv<64, true>,  cudaFuncAttributeMaxDynamicSharedMemorySize, SM2);

    k_zero_stats<<<1, 256>>>();
    k_zero<<<4096, 256>>>((uint4*)xb1, (size_t)16 * 132 * 260 * 64 / 8);
    k_zero<<<4096, 256>>>((uint4*)xb2, (size_t)16 * 134 * 262 * 64 / 8);
    k_pack<<<(2 * 9 * 2 * 128 * 40 + 255) / 256, 256>>>(w1, ap1, 32, 40);
    k_pack<<<(2 * 9 * 2 * 128 * 72 + 255) / 256, 256>>>(w2, ap2, 64, 72);
    k_tin<<<16 * 128, 256>>>((const float4*)x, xb1);

    k_conv<32, false><<<dim3(3, 65, 32), 256, SM1>>>(xb1, ap1, b1, a1h, a1w, nullptr,
                                                     xb2, stats, HO1, WO1, 132, 260, 134, 262);
    k_finalize<<<1, 64>>>(stats, g1, be1, st, (float)TOT1);

    k_conv<64, true><<<dim3(3, 66, 32), 256, SM2>>>(xb2, ap2, b2, a2h, a2w, st,
                                                    y2, stats + 128, HO2, WO2, 134, 262, 136, 264);
    k_finalize<<<1, 64>>>(stats + 128, g2, be2, st + 128, (float)TOT2);

    k_pool<<<(16 * 44 * 86 * 8 + 255) / 256, 256>>>(y2, st + 128, (float*)d_out);
}

// round 10
// speedup vs baseline: 3.6200x; 2.1625x over previous
#include <cuda_runtime.h>
#include <cuda_fp16.h>
#include <math.h>
#include <stdint.h>

#define EPSBN 1e-5f

// layer geometry
#define HO1 130
#define WO1 258
#define HO2 132
#define WO2 260
#define TOT1 (16 * HO1 * WO1)
#define TOT2 (16 * HO2 * WO2)

// fp16 NHWC halo buffers (64 ch, 2-px halo each side).
// Halos MUST be re-zeroed every kernel_launch call: the harness dirties device
// memory between the correctness run and timed replays (R8 post-mortem).
__device__ __half g_xb1[(size_t)16 * 132 * 260 * 64];
__device__ __half g_xb2[(size_t)16 * 134 * 262 * 64];
__device__ __half g_y2 [(size_t)16 * 136 * 264 * 64];
// packed A blocks: [mh(2)][tap(9)][m(128)][KCI+8] fp16 (single fp16)
__device__ __half g_apk1[2 * 9 * 128 * 40];
__device__ __half g_apk2[2 * 9 * 128 * 72];
__device__ float  g_stats[4 * 64];
__device__ float  g_st[4 * 64];

// ---- helpers ----
__device__ __forceinline__ uint32_t smem_u32(const void* p) {
    uint32_t a;
    asm("{ .reg .u64 t; cvta.to.shared.u64 t, %1; cvt.u32.u64 %0, t; }" : "=r"(a) : "l"(p));
    return a;
}
#define LDSM4(r, addr) \
    asm volatile("ldmatrix.sync.aligned.m8n8.x4.shared.b16 {%0,%1,%2,%3}, [%4];" \
        : "=r"((r)[0]), "=r"((r)[1]), "=r"((r)[2]), "=r"((r)[3]) : "r"(addr))
#define LDSM2(r, addr) \
    asm volatile("ldmatrix.sync.aligned.m8n8.x2.shared.b16 {%0,%1}, [%2];" \
        : "=r"((r)[0]), "=r"((r)[1]) : "r"(addr))

__device__ __forceinline__ void hmma(float* c, const uint32_t* a, const uint32_t* b) {
    asm volatile(
        "mma.sync.aligned.m16n8k16.row.col.f32.f16.f16.f32 "
        "{%0,%1,%2,%3}, {%4,%5,%6,%7}, {%8,%9}, {%0,%1,%2,%3};"
        : "+f"(c[0]), "+f"(c[1]), "+f"(c[2]), "+f"(c[3])
        : "r"(a[0]), "r"(a[1]), "r"(a[2]), "r"(a[3]), "r"(b[0]), "r"(b[1]));
}
__device__ __forceinline__ void cpa16(uint32_t d, const void* s) {
    asm volatile("cp.async.cg.shared.global [%0], [%1], 16;" :: "r"(d), "l"(s));
}
#define CP_COMMIT() asm volatile("cp.async.commit_group;" ::: "memory")
#define CP_WAIT1()  asm volatile("cp.async.wait_group 1;" ::: "memory")

// ---- aux kernels ----
__global__ void k_zero(uint4* p, size_t n) {
    size_t i = (size_t)blockIdx.x * blockDim.x + threadIdx.x;
    size_t st = (size_t)gridDim.x * blockDim.x;
    uint4 z = make_uint4(0, 0, 0, 0);
    for (; i < n; i += st) p[i] = z;
}
__global__ void k_zero_stats() {
    if (threadIdx.x < 4 * 64) g_stats[threadIdx.x] = 0.f;
}
__global__ void k_finalize(const float* __restrict__ sums, const float* __restrict__ gam,
                           const float* __restrict__ bet, float* __restrict__ st, float N) {
    int c = threadIdx.x;
    if (c < 64) {
        float mean = sums[c] / N;
        float var  = sums[64 + c] / N - mean * mean;
        float s    = gam[c] * rsqrtf(var + EPSBN);
        st[c]      = s;
        st[64 + c] = bet[c] - mean * s;
    }
}
// pack weights [r][64][CIN][3][3] fp32 -> [mh][tap][m=o*4+r][CIN+8] fp16
__global__ void k_pack(const float* __restrict__ w, __half* __restrict__ apk,
                       int CIN, int PR) {
    int idx = blockIdx.x * 256 + threadIdx.x;
    const int TOTP = 2 * 9 * 128 * PR;
    if (idx >= TOTP) return;
    int kq = idx % PR;
    int m  = (idx / PR) % 128;
    int kk = (idx / (PR * 128)) % 9;
    int mh = idx / (PR * 128 * 9);
    int r = m & 3, o = mh * 32 + (m >> 2);
    int kh = kk / 3, kw = kk - kh * 3;
    float v = 0.f;
    if (kq < CIN) v = w[(((r * 64 + o) * CIN + kq) * 3 + kh) * 3 + kw];
    apk[idx] = __float2half(v);
}
// x NCHW fp32 -> xb1 NHWC fp16 halo (channels 32..63 stay zero)
__global__ __launch_bounds__(256) void k_tin(const float4* __restrict__ x4,
                                             __half* __restrict__ xb) {
    __shared__ __half ts[32][264];
    int tid = threadIdx.x;
    int b = blockIdx.x >> 7;
    int h = blockIdx.x & 127;
#pragma unroll
    for (int it = 0; it < 8; ++it) {
        int idx = tid + it * 256;
        int c = idx >> 6, w4 = idx & 63;
        float4 v = x4[((size_t)(b * 32 + c) * 128 + h) * 64 + w4];
        ts[c][w4 * 4 + 0] = __float2half(v.x);
        ts[c][w4 * 4 + 1] = __float2half(v.y);
        ts[c][w4 * 4 + 2] = __float2half(v.z);
        ts[c][w4 * 4 + 3] = __float2half(v.w);
    }
    __syncthreads();
    int w = tid;
    __half tmp[32];
#pragma unroll
    for (int c = 0; c < 32; ++c) tmp[c] = ts[c][w];
    uint4* dst = (uint4*)(xb + ((size_t)(b * 132 + h + 2) * 260 + (w + 2)) * 64);
#pragma unroll
    for (int q = 0; q < 4; ++q) dst[q] = ((uint4*)tmp)[q];
}
// BN2 + ReLU + 3x3/3 maxpool -> NCHW fp32 out
__global__ void k_pool(const __half* __restrict__ y2, const float* __restrict__ st,
                       float* __restrict__ out) {
    int idx = blockIdx.x * blockDim.x + threadIdx.x;
    const int n = 16 * 44 * 86 * 8;
    if (idx >= n) return;
    int c8 = idx & 7;
    int rem = idx >> 3;
    int ow = rem % 86; rem /= 86;
    int oh = rem % 44;
    int b = rem / 44;
    float acc[8];
#pragma unroll
    for (int j = 0; j < 8; ++j) acc[j] = 0.f;
#pragma unroll
    for (int kh = 0; kh < 3; ++kh)
#pragma unroll
        for (int kw = 0; kw < 3; ++kw) {
            const __half* p = y2 + ((size_t)(b * 136 + oh * 3 + kh + 2) * 264
                                    + (ow * 3 + kw + 2)) * 64 + c8 * 8;
            uint4 v = *(const uint4*)p;
            const __half* hv = (const __half*)&v;
#pragma unroll
            for (int j = 0; j < 8; ++j) {
                int c = c8 * 8 + j;
                float f = __half2float(hv[j]) * st[c] + st[64 + c];
                acc[j] = fmaxf(acc[j], fmaxf(f, 0.f));
            }
        }
#pragma unroll
    for (int j = 0; j < 8; ++j) {
        int c = c8 * 8 + j;
        out[((size_t)(b * 64 + c) * 44 + oh) * 86 + ow] = acc[j];
    }
}

// ---- main conv: warp-MMA implicit GEMM, single-fp16 weights ----
// CTA: one output row h, 144 px (2 tiles/row), M=128 (=32 o x 4 r, mh half).
// 8 warps: warp tile m32 x n72 (9 B fragments). cp.async double-buffered A.
// FUSED: apply BN(stl)+ReLU of previous layer while staging B (interior only).
template<int KCI, bool FUSED>
__global__ __launch_bounds__(256, 2)
void k_conv(const __half* __restrict__ xb, const __half* __restrict__ apk,
            const float* __restrict__ bias, const float* __restrict__ ah,
            const float* __restrict__ aw, const float* __restrict__ stl,
            __half* __restrict__ yb, float* __restrict__ stats,
            int HO, int WO, int HpIn, int WpIn, int HpOut, int WpOut)
{
    constexpr int NT     = 144;                 // px per CTA
    constexpr int STRW   = 146;                 // strip width (px + 2 halo)
    constexpr int PITCH  = 2 * KCI + 16;        // bytes per smem row
    constexpr int PRH    = KCI + 8;             // halfs per packed-A row
    constexpr int ACH    = 128 * PITCH;         // per-tap A chunk
    constexpr int KSTEPS = KCI / 16;
    constexpr int BU4    = KCI / 8;             // uint4 per B px
    constexpr int SMB  = 0;
    constexpr int SMA  = 3 * STRW * PITCH;
    constexpr int SMCW = SMA + 2 * ACH;
    constexpr int SMBI = SMCW + 4 * NT * 4;
    constexpr int SMY  = SMBI + 128;
    constexpr int SMPP = SMY + NT * 32 * 2;

    extern __shared__ char smraw[];
    char* bsm = smraw + SMB;
    float* cws = (float*)(smraw + SMCW);        // [r4][144]
    float* bias_s = (float*)(smraw + SMBI);
    __half* ysm = (__half*)(smraw + SMY);       // [144 px][32 ch]
    float2* pp = (float2*)(smraw + SMPP);
    const uint32_t SB = smem_u32(smraw);

    const int tid = threadIdx.x;
    const int lane = tid & 31;
    const int wid = tid >> 5;
    const int h  = blockIdx.y;
    const int w0 = blockIdx.x * NT;
    const int b  = blockIdx.z >> 1;
    const int mh = blockIdx.z & 1;
    const int npx = min(NT, WO - w0);

    // prefetch A taps 0,1 (cp.async, double buffer)
    {
        constexpr int NU = ACH / 16;
#pragma unroll
        for (int t = 0; t < 2; ++t) {
            const char* src = (const char*)(apk + (size_t)((mh * 9 + t)) * 128 * PRH);
            uint32_t dst = SB + SMA + t * ACH;
            for (int i = tid; i < NU; i += 256) cpa16(dst + i * 16, src + i * 16);
            CP_COMMIT();
        }
    }

    // stage B: 3 input-row strips x 146 px (BN+ReLU fused if FUSED, interior only)
    for (int i = tid; i < 3 * STRW * BU4; i += 256) {
        int q = i % BU4;
        int p = i / BU4;
        int strip = p / STRW, c = p - strip * STRW;
        int row = h + strip;
        int col = min(w0 + c, WpIn - 1);
        uint4 v = *((const uint4*)(xb + ((size_t)(b * HpIn + row) * WpIn + col) * 64) + q);
        if (FUSED) {
            if (row >= 2 && row < HpIn - 2 && col >= 2 && col < WpIn - 2) {
                __half* hv = (__half*)&v;
#pragma unroll
                for (int j = 0; j < 8; ++j) {
                    int ch = q * 8 + j;
                    float f = __half2float(hv[j]) * stl[ch] + stl[64 + ch];
                    hv[j] = __float2half(fmaxf(f, 0.f));
                }
            }
        }
        *(uint4*)(bsm + p * PITCH + q * 16) = v;
    }
    // combining weights (softmax over rank) per pixel
    if (tid < NT) {
        int w = min(w0 + tid, WO - 1);
        float lg[4], mx = -1e30f;
#pragma unroll
        for (int r = 0; r < 4; ++r) { lg[r] = ah[r * HO + h] + aw[r * WO + w]; mx = fmaxf(mx, lg[r]); }
        float es = 0.f;
#pragma unroll
        for (int r = 0; r < 4; ++r) { lg[r] = expf(lg[r] - mx); es += lg[r]; }
        float inv = 1.f / es;
#pragma unroll
        for (int r = 0; r < 4; ++r) cws[r * NT + tid] = lg[r] * inv;
    }
    if (tid < 32) bias_s[tid] = bias[mh * 32 + tid];

    float acc[2][9][4];
#pragma unroll
    for (int mi = 0; mi < 2; ++mi)
#pragma unroll
        for (int ni = 0; ni < 9; ++ni)
#pragma unroll
            for (int c = 0; c < 4; ++c) acc[mi][ni][c] = 0.f;

    const int moff = (wid >> 1) * 32;
    const int noff = (wid & 1) * 72;
    const int arow = lane & 15;
    const int acol16 = (lane >> 4) * 16;
    const int brow = (lane & 7) + ((lane >> 4) << 3);
    const int bcol16 = ((lane >> 3) & 1) * 16;
    const uint32_t a_base0 = SB + SMA + (moff + arow) * PITCH + acol16;

#pragma unroll 1
    for (int kk = 0; kk < 9; ++kk) {
        CP_WAIT1();
        __syncthreads();
        const int kh = kk / 3, kw = kk - (kk / 3) * 3;
        const uint32_t a_base = a_base0 + (kk & 1) * ACH;
        const uint32_t b_base = SB + (kh * STRW + noff + kw + brow) * PITCH + bcol16;
#pragma unroll
        for (int s = 0; s < KSTEPS; ++s) {
            uint32_t af[2][4];
            LDSM4(af[0], a_base + s * 32);
            LDSM4(af[1], a_base + 16 * PITCH + s * 32);
            uint32_t bf[4][4];
            uint32_t b8[2];
#pragma unroll
            for (int g = 0; g < 4; ++g)
                LDSM4(bf[g], b_base + g * (16 * PITCH) + s * 32);
            LDSM2(b8, b_base + 64 * PITCH + s * 32);
#pragma unroll
            for (int mi = 0; mi < 2; ++mi) {
#pragma unroll
                for (int n8 = 0; n8 < 8; ++n8)
                    hmma(acc[mi][n8], af[mi], &bf[n8 >> 1][(n8 & 1) * 2]);
                hmma(acc[mi][8], af[mi], b8);
            }
        }
        __syncthreads();
        if (kk + 2 < 9) {
            constexpr int NU = ACH / 16;
            const char* src = (const char*)(apk + (size_t)((mh * 9 + kk + 2)) * 128 * PRH);
            uint32_t dst = SB + SMA + (kk & 1) * ACH;
            for (int i = tid; i < NU; i += 256) cpa16(dst + i * 16, src + i * 16);
            CP_COMMIT();
        }
    }

    // ---- epilogue: rank combine (shfl over r), bias, fp16 to ysm ----
    const int r4 = (lane >> 2) & 3;
    const bool lead = (r4 == 0);
#pragma unroll
    for (int mi = 0; mi < 2; ++mi)
#pragma unroll
        for (int ni = 0; ni < 9; ++ni) {
            int px0 = noff + 8 * ni + 2 * (lane & 3);
            float v0 = acc[mi][ni][0] * cws[r4 * NT + px0];
            float v1 = acc[mi][ni][1] * cws[r4 * NT + px0 + 1];
            float v2 = acc[mi][ni][2] * cws[r4 * NT + px0];
            float v3 = acc[mi][ni][3] * cws[r4 * NT + px0 + 1];
            v0 += __shfl_xor_sync(~0u, v0, 4); v0 += __shfl_xor_sync(~0u, v0, 8);
            v1 += __shfl_xor_sync(~0u, v1, 4); v1 += __shfl_xor_sync(~0u, v1, 8);
            v2 += __shfl_xor_sync(~0u, v2, 4); v2 += __shfl_xor_sync(~0u, v2, 8);
            v3 += __shfl_xor_sync(~0u, v3, 4); v3 += __shfl_xor_sync(~0u, v3, 8);
            if (lead) {
                int o0 = (moff + 16 * mi + (lane >> 2)) >> 2;
                int o2 = o0 + 2;
                __half* yr = ysm + px0 * 32;
                yr[o0]      = __float2half(v0 + bias_s[o0]);
                yr[32 + o0] = __float2half(v1 + bias_s[o0]);
                yr[o2]      = __float2half(v2 + bias_s[o2]);
                yr[32 + o2] = __float2half(v3 + bias_s[o2]);
            }
        }
    __syncthreads();

    // BN stats (valid px only)
    {
        int ol = tid & 31, pb = tid >> 5;
        float s0 = 0.f, s1 = 0.f;
#pragma unroll
        for (int jj = 0; jj < 18; ++jj) {
            int j = pb * 18 + jj;
            if (j < npx) {
                float v = __half2float(ysm[j * 32 + ol]);
                s0 += v; s1 += v * v;
            }
        }
        pp[pb * 32 + ol] = make_float2(s0, s1);
    }
    __syncthreads();
    if (tid < 32) {
        float a0 = 0.f, a1 = 0.f;
#pragma unroll
        for (int pb2 = 0; pb2 < 8; ++pb2) {
            float2 u = pp[pb2 * 32 + tid];
            a0 += u.x; a1 += u.y;
        }
        atomicAdd(&stats[mh * 32 + tid], a0);
        atomicAdd(&stats[64 + mh * 32 + tid], a1);
    }
    // store NHWC fp16 (this CTA's 32-ch half), halo offset +2
    for (int i = tid; i < npx * 4; i += 256) {
        int p = i >> 2, q = i & 3;
        *(uint4*)(yb + ((size_t)(b * HpOut + h + 2) * WpOut + (w0 + p + 2)) * 64
                  + mh * 32 + q * 8) = *(const uint4*)(ysm + p * 32 + q * 8);
    }
}

extern "C" void kernel_launch(void* const* d_in, const int* in_sizes, int n_in,
                              void* d_out, int out_size) {
    const float* x   = (const float*)d_in[0];
    const float* w1  = (const float*)d_in[1];
    const float* b1  = (const float*)d_in[2];
    const float* a1h = (const float*)d_in[3];
    const float* a1w = (const float*)d_in[4];
    const float* g1  = (const float*)d_in[5];
    const float* be1 = (const float*)d_in[6];
    const float* w2  = (const float*)d_in[7];
    const float* b2  = (const float*)d_in[8];
    const float* a2h = (const float*)d_in[9];
    const float* a2w = (const float*)d_in[10];
    const float* g2  = (const float*)d_in[11];
    const float* be2 = (const float*)d_in[12];

    __half *xb1, *xb2, *y2, *ap1, *ap2;
    float *stats, *st;
    cudaGetSymbolAddress((void**)&xb1, g_xb1);
    cudaGetSymbolAddress((void**)&xb2, g_xb2);
    cudaGetSymbolAddress((void**)&y2, g_y2);
    cudaGetSymbolAddress((void**)&ap1, g_apk1);
    cudaGetSymbolAddress((void**)&ap2, g_apk2);
    cudaGetSymbolAddress((void**)&stats, g_stats);
    cudaGetSymbolAddress((void**)&st, g_st);

    // smem sizes: 3*146*PITCH + 2*128*PITCH + 4*144*4 + 128 + 144*64 + 2048
    const int SM1 = 3 * 146 * 80 + 2 * 128 * 80 + 2304 + 128 + 9216 + 2048;    // 69,216
    const int SM2 = 3 * 146 * 144 + 2 * 128 * 144 + 2304 + 128 + 9216 + 2048;  // 113,632
    cudaFuncSetAttribute(k_conv<32, false>, cudaFuncAttributeMaxDynamicSharedMemorySize, SM1);
    cudaFuncSetAttribute(k_conv<64, true>,  cudaFuncAttributeMaxDynamicSharedMemorySize, SM2);

    k_zero_stats<<<1, 256>>>();
    // re-zero halo buffers EVERY call (harness dirties device memory pre-timing;
    // interiors are fully rewritten in-call, halos must be restored to zero)
    k_zero<<<4096, 256>>>((uint4*)xb1, (size_t)16 * 132 * 260 * 64 / 8);
    k_zero<<<4096, 256>>>((uint4*)xb2, (size_t)16 * 134 * 262 * 64 / 8);
    k_pack<<<(2 * 9 * 128 * 40 + 255) / 256, 256>>>(w1, ap1, 32, 40);
    k_pack<<<(2 * 9 * 128 * 72 + 255) / 256, 256>>>(w2, ap2, 64, 72);
    k_tin<<<16 * 128, 256>>>((const float4*)x, xb1);

    k_conv<32, false><<<dim3(2, HO1, 32), 256, SM1>>>(xb1, ap1, b1, a1h, a1w, nullptr,
                                                      xb2, stats, HO1, WO1, 132, 260, 134, 262);
    k_finalize<<<1, 64>>>(stats, g1, be1, st, (float)TOT1);

    k_conv<64, true><<<dim3(2, HO2, 32), 256, SM2>>>(xb2, ap2, b2, a2h, a2w, st,
                                                     y2, stats + 128, HO2, WO2, 134, 262, 136, 264);
    k_finalize<<<1, 64>>>(stats + 128, g2, be2, st + 128, (float)TOT2);

    k_pool<<<(16 * 44 * 86 * 8 + 255) / 256, 256>>>(y2, st + 128, (float*)d_out);
}